// round 5
// baseline (speedup 1.0000x reference)
#include <cuda_runtime.h>
#include <math.h>

#define HH 2048
#define WW 2048
#define NPB (HH*WW)            // 4,194,304 elems per batch
#define NF4 (NPB/4)            // 1,048,576 float4 per batch
#define BATCH 8
#define BPB 148                // blocks per batch -> 1184 blocks = 8 per SM exactly
#define T1 256                 // threads per block
#define NBLK (BPB*BATCH)       // 1184 total blocks
#define STRIDE (BPB*T1)        // 37888 threads per batch (float4 units)
#define WIN 5

// Scratch (device globals — no allocation in kernel_launch)
__device__ float g_pmax[NBLK];
__device__ int   g_pidx[NBLK];
__device__ float g_psum[NBLK];
__device__ float g_psq [NBLK];
__device__ int   g_pcnt[NBLK];
__device__ int   g_counter;      // zero-init; reset by the last block each run

__global__ void __launch_bounds__(T1) psr_fused(const float* __restrict__ resp,
                                                float* __restrict__ out) {
    const int b   = blockIdx.y;
    const int tid = blockIdx.x * T1 + threadIdx.x;       // 0..STRIDE-1 within batch
    const float4* __restrict__ p = (const float4*)(resp + (size_t)b * NPB);

    float mx = -INFINITY;
    int   midx = 0;
    float s = 0.f, sq = 0.f; int c = 0;

    #pragma unroll 4
    for (int i = tid; i < NF4; i += STRIDE) {
        const float4 v = p[i];
        float m;
        m = fmaxf(v.x, 0.f); s += m; sq = fmaf(m, m, sq); c += (v.x > 0.f);
        m = fmaxf(v.y, 0.f); s += m; sq = fmaf(m, m, sq); c += (v.y > 0.f);
        m = fmaxf(v.z, 0.f); s += m; sq = fmaf(m, m, sq); c += (v.z > 0.f);
        m = fmaxf(v.w, 0.f); s += m; sq = fmaf(m, m, sq); c += (v.w > 0.f);
        const float vm = fmaxf(fmaxf(v.x, v.y), fmaxf(v.z, v.w));
        if (vm > mx) {                                   // rare
            mx = vm;
            int comp = 3;
            if (v.z == vm) comp = 2;
            if (v.y == vm) comp = 1;
            if (v.x == vm) comp = 0;
            midx = i * 4 + comp;
        }
    }

    // ---- intra-warp reduce ----
    const unsigned FULL = 0xFFFFFFFFu;
    #pragma unroll
    for (int off = 16; off > 0; off >>= 1) {
        float om = __shfl_down_sync(FULL, mx, off);
        int   oi = __shfl_down_sync(FULL, midx, off);
        if (om > mx || (om == mx && oi < midx)) { mx = om; midx = oi; }
        s  += __shfl_down_sync(FULL, s,  off);
        sq += __shfl_down_sync(FULL, sq, off);
        c  += __shfl_down_sync(FULL, c,  off);
    }

    // ---- cross-warp reduce via smem (8 warps) ----
    __shared__ float wmax[8]; __shared__ int widx[8];
    __shared__ float wsum[8]; __shared__ float wsq[8]; __shared__ int wcnt[8];
    const int lane = threadIdx.x & 31;
    const int wid  = threadIdx.x >> 5;
    if (lane == 0) { wmax[wid] = mx; widx[wid] = midx; wsum[wid] = s; wsq[wid] = sq; wcnt[wid] = c; }
    __syncthreads();

    if (wid == 0) {
        mx   = (lane < 8) ? wmax[lane] : -INFINITY;
        midx = (lane < 8) ? widx[lane] : 0x7FFFFFFF;
        s    = (lane < 8) ? wsum[lane] : 0.f;
        sq   = (lane < 8) ? wsq[lane]  : 0.f;
        c    = (lane < 8) ? wcnt[lane] : 0;
        #pragma unroll
        for (int off = 4; off > 0; off >>= 1) {
            float om = __shfl_down_sync(FULL, mx, off);
            int   oi = __shfl_down_sync(FULL, midx, off);
            if (om > mx || (om == mx && oi < midx)) { mx = om; midx = oi; }
            s  += __shfl_down_sync(FULL, s,  off);
            sq += __shfl_down_sync(FULL, sq, off);
            c  += __shfl_down_sync(FULL, c,  off);
        }
        if (lane == 0) {
            const int o = b * BPB + blockIdx.x;
            g_pmax[o] = mx; g_pidx[o] = midx; g_psum[o] = s; g_psq[o] = sq; g_pcnt[o] = c;
        }
    }

    // ---- last-block-done: finalize in this kernel ----
    __shared__ int is_last;
    __threadfence();
    __syncthreads();
    if (threadIdx.x == 0) {
        int prev = atomicAdd(&g_counter, 1);
        is_last = (prev == NBLK - 1);
    }
    __syncthreads();
    if (!is_last) return;

    // One warp per batch (8 warps x 32 lanes).
    __shared__ float spsr[8];
    {
        const int w = threadIdx.x >> 5;     // batch
        const int l = threadIdx.x & 31;

        float bmx = -INFINITY; int bmi = 0x7FFFFFFF;
        double bs = 0.0, bq = 0.0; int bc = 0;
        #pragma unroll
        for (int j = 0; j < BPB; j += 32) {          // 5 strips, last partial
            const int jj = j + l;
            if (jj < BPB) {
                const int o = w * BPB + jj;
                float pm = __ldcg(&g_pmax[o]); int pi = __ldcg(&g_pidx[o]);
                if (pm > bmx || (pm == bmx && pi < bmi)) { bmx = pm; bmi = pi; }
                bs += (double)__ldcg(&g_psum[o]);
                bq += (double)__ldcg(&g_psq[o]);
                bc += __ldcg(&g_pcnt[o]);
            }
        }
        #pragma unroll
        for (int off = 16; off > 0; off >>= 1) {
            float om = __shfl_down_sync(FULL, bmx, off);
            int   oi = __shfl_down_sync(FULL, bmi, off);
            if (om > bmx || (om == bmx && oi < bmi)) { bmx = om; bmi = oi; }
            bs += __shfl_down_sync(FULL, bs, off);
            bq += __shfl_down_sync(FULL, bq, off);
            bc += __shfl_down_sync(FULL, bc, off);
        }
        bmi = __shfl_sync(FULL, bmi, 0);
        const int cy = bmi / WW, cx = bmi % WW;

        // 11x11 window correction, 121 elems over 32 lanes (4 indep loads/lane)
        double ws = 0.0, wq = 0.0; int wc = 0;
        #pragma unroll
        for (int t = 0; t < 4; t++) {
            const int it = l + t * 32;
            if (it < (2*WIN+1)*(2*WIN+1)) {
                const int y = cy + it / (2*WIN+1) - WIN;
                const int x = cx + it % (2*WIN+1) - WIN;
                if (y >= 0 && y < HH && x >= 0 && x < WW) {
                    const float v = resp[(size_t)w * NPB + (size_t)y * WW + x];
                    if (v > 0.f) { ws += (double)v; wq += (double)v * (double)v; wc++; }
                }
            }
        }
        #pragma unroll
        for (int off = 16; off > 0; off >>= 1) {
            ws += __shfl_down_sync(FULL, ws, off);
            wq += __shfl_down_sync(FULL, wq, off);
            wc += __shfl_down_sync(FULL, wc, off);
        }
        if (l == 0) {
            const double n    = (double)(bc - wc);
            const double sum  = bs - ws;
            const double sqs  = bq - wq;
            const double mean = sum / n;
            const double var  = (sqs - n * mean * mean) / (n - 1.0);
            const float  stdv = (float)sqrt(var);
            spsr[w] = (float)(((double)bmx - mean)) / (stdv + 1e-5f);
        }
    }
    __syncthreads();
    if (threadIdx.x == 0) {
        float acc = 0.f;
        #pragma unroll
        for (int i = 0; i < BATCH; i++) acc += spsr[i];
        out[0] = acc / (float)BATCH;
        g_counter = 0;   // only block left; safe reset for next graph replay
    }
}

extern "C" void kernel_launch(void* const* d_in, const int* in_sizes, int n_in,
                              void* d_out, int out_size) {
    const float* resp = (const float*)d_in[0];
    float* out = (float*)d_out;
    dim3 grid(BPB, BATCH);
    psr_fused<<<grid, T1>>>(resp, out);
}

// round 6
// speedup vs baseline: 1.1398x; 1.1398x over previous
#include <cuda_runtime.h>
#include <math.h>

#define HH 2048
#define WW 2048
#define NPB (HH*WW)            // 4,194,304 elems per batch
#define BATCH 8
#define BPB 128                // blocks per batch
#define T1 256                 // threads per block
#define NBLK (BPB*BATCH)       // 1024 total blocks
#define STRIDE (BPB*T1)        // 32768 threads per batch (float4 units)
#define ITERS (NPB/4/STRIDE)   // 32 float4 loads per thread, exact
#define WIN 5

// Scratch (device globals — no allocation in kernel_launch)
__device__ float g_pmax[NBLK];
__device__ int   g_pidx[NBLK];
__device__ float g_psum[NBLK];
__device__ float g_psq [NBLK];
__device__ int   g_pcnt[NBLK];
__device__ int   g_counter;      // zero-init; reset by the last block each run

__device__ __forceinline__ unsigned long long pack2(float lo, float hi) {
    unsigned long long r;
    asm("mov.b64 %0, {%1, %2};" : "=l"(r) : "r"(__float_as_uint(lo)), "r"(__float_as_uint(hi)));
    return r;
}
__device__ __forceinline__ void unpack2(unsigned long long v, float& lo, float& hi) {
    unsigned a, b;
    asm("mov.b64 {%0, %1}, %2;" : "=r"(a), "=r"(b) : "l"(v));
    lo = __uint_as_float(a); hi = __uint_as_float(b);
}
__device__ __forceinline__ unsigned long long add2(unsigned long long a, unsigned long long b) {
    unsigned long long r;
    asm("add.rn.f32x2 %0, %1, %2;" : "=l"(r) : "l"(a), "l"(b));
    return r;
}
__device__ __forceinline__ unsigned long long fma2(unsigned long long a, unsigned long long b,
                                                   unsigned long long c) {
    unsigned long long r;
    asm("fma.rn.f32x2 %0, %1, %2, %3;" : "=l"(r) : "l"(a), "l"(b), "l"(c));
    return r;
}

__global__ void __launch_bounds__(T1, 8) psr_fused(const float* __restrict__ resp,
                                                   float* __restrict__ out) {
    const int b   = blockIdx.y;
    const int tid = blockIdx.x * T1 + threadIdx.x;       // 0..STRIDE-1 within batch
    const float4* __restrict__ p = (const float4*)(resp + (size_t)b * NPB);

    float mx = -INFINITY;                                // best float4-max so far
    int   mi4 = 0;                                       // its float4 index (within batch)
    unsigned long long s01 = 0, s23 = 0, sq01 = 0, sq23 = 0;  // packed f32x2 accumulators
    int c0 = 0, c1 = 0;

    #pragma unroll 4
    for (int k = 0; k < ITERS; k++) {
        const int i = tid + k * STRIDE;
        const float4 v = p[i];
        // clamped values
        const float m0 = fmaxf(v.x, 0.f);
        const float m1 = fmaxf(v.y, 0.f);
        const float m2 = fmaxf(v.z, 0.f);
        const float m3 = fmaxf(v.w, 0.f);
        const unsigned long long m01 = pack2(m0, m1);
        const unsigned long long m23 = pack2(m2, m3);
        s01  = add2(s01, m01);
        s23  = add2(s23, m23);
        sq01 = fma2(m01, m01, sq01);
        sq23 = fma2(m23, m23, sq23);
        c0 += (v.x > 0.f) + (v.z > 0.f);
        c1 += (v.y > 0.f) + (v.w > 0.f);
        // branchless coarse argmax (float4 granularity, first-occurrence via strict >)
        const float vm = fmaxf(fmaxf(v.x, v.y), fmaxf(v.z, v.w));
        const bool gt = vm > mx;
        mx  = gt ? vm : mx;
        mi4 = gt ? i  : mi4;
    }

    // merge packed accumulators
    float sa, sb, s, sqa, sqb, sq;
    unpack2(s01, sa, sb);  s  = sa + sb;
    unpack2(s23, sa, sb);  s += sa + sb;
    unpack2(sq01, sqa, sqb); sq  = sqa + sqb;
    unpack2(sq23, sqa, sqb); sq += sqa + sqb;
    int c = c0 + c1;

    // ---- intra-warp reduce ----
    const unsigned FULL = 0xFFFFFFFFu;
    #pragma unroll
    for (int off = 16; off > 0; off >>= 1) {
        float om = __shfl_down_sync(FULL, mx, off);
        int   oi = __shfl_down_sync(FULL, mi4, off);
        if (om > mx || (om == mx && oi < mi4)) { mx = om; mi4 = oi; }
        s  += __shfl_down_sync(FULL, s,  off);
        sq += __shfl_down_sync(FULL, sq, off);
        c  += __shfl_down_sync(FULL, c,  off);
    }

    // ---- cross-warp reduce via smem (8 warps) ----
    __shared__ float wmax[8]; __shared__ int widx[8];
    __shared__ float wsum[8]; __shared__ float wsq[8]; __shared__ int wcnt[8];
    const int lane = threadIdx.x & 31;
    const int wid  = threadIdx.x >> 5;
    if (lane == 0) { wmax[wid] = mx; widx[wid] = mi4; wsum[wid] = s; wsq[wid] = sq; wcnt[wid] = c; }
    __syncthreads();

    if (wid == 0) {
        mx  = (lane < 8) ? wmax[lane] : -INFINITY;
        mi4 = (lane < 8) ? widx[lane] : 0x7FFFFFFF;
        s   = (lane < 8) ? wsum[lane] : 0.f;
        sq  = (lane < 8) ? wsq[lane]  : 0.f;
        c   = (lane < 8) ? wcnt[lane] : 0;
        #pragma unroll
        for (int off = 4; off > 0; off >>= 1) {
            float om = __shfl_down_sync(FULL, mx, off);
            int   oi = __shfl_down_sync(FULL, mi4, off);
            if (om > mx || (om == mx && oi < mi4)) { mx = om; mi4 = oi; }
            s  += __shfl_down_sync(FULL, s,  off);
            sq += __shfl_down_sync(FULL, sq, off);
            c  += __shfl_down_sync(FULL, c,  off);
        }
        if (lane == 0) {
            // resolve the winning component once per block
            const float4 v = __ldg(p + mi4);
            int comp = 3;
            if (v.z == mx) comp = 2;
            if (v.y == mx) comp = 1;
            if (v.x == mx) comp = 0;
            const int o = b * BPB + blockIdx.x;
            g_pmax[o] = mx; g_pidx[o] = mi4 * 4 + comp;
            g_psum[o] = s;  g_psq[o]  = sq; g_pcnt[o] = c;
        }
    }

    // ---- last-block-done: finalize in this kernel ----
    __shared__ int is_last;
    __threadfence();
    __syncthreads();
    if (threadIdx.x == 0) {
        int prev = atomicAdd(&g_counter, 1);
        is_last = (prev == NBLK - 1);
    }
    __syncthreads();
    if (!is_last) return;

    // One warp per batch (8 warps x 32 lanes).
    __shared__ float spsr[8];
    {
        const int w = threadIdx.x >> 5;     // batch
        const int l = threadIdx.x & 31;

        float bmx = -INFINITY; int bmi = 0x7FFFFFFF;
        double bs = 0.0, bq = 0.0; int bc = 0;
        #pragma unroll
        for (int j = 0; j < BPB; j += 32) {
            const int o = w * BPB + j + l;
            float pm = __ldcg(&g_pmax[o]); int pi = __ldcg(&g_pidx[o]);
            if (pm > bmx || (pm == bmx && pi < bmi)) { bmx = pm; bmi = pi; }
            bs += (double)__ldcg(&g_psum[o]);
            bq += (double)__ldcg(&g_psq[o]);
            bc += __ldcg(&g_pcnt[o]);
        }
        #pragma unroll
        for (int off = 16; off > 0; off >>= 1) {
            float om = __shfl_down_sync(FULL, bmx, off);
            int   oi = __shfl_down_sync(FULL, bmi, off);
            if (om > bmx || (om == bmx && oi < bmi)) { bmx = om; bmi = oi; }
            bs += __shfl_down_sync(FULL, bs, off);
            bq += __shfl_down_sync(FULL, bq, off);
            bc += __shfl_down_sync(FULL, bc, off);
        }
        bmi = __shfl_sync(FULL, bmi, 0);
        const int cy = bmi / WW, cx = bmi % WW;

        // 11x11 window correction, 121 elems over 32 lanes
        double ws = 0.0, wq = 0.0; int wc = 0;
        #pragma unroll
        for (int t = 0; t < 4; t++) {
            const int it = l + t * 32;
            if (it < (2*WIN+1)*(2*WIN+1)) {
                const int y = cy + it / (2*WIN+1) - WIN;
                const int x = cx + it % (2*WIN+1) - WIN;
                if (y >= 0 && y < HH && x >= 0 && x < WW) {
                    const float v = resp[(size_t)w * NPB + (size_t)y * WW + x];
                    if (v > 0.f) { ws += (double)v; wq += (double)v * (double)v; wc++; }
                }
            }
        }
        #pragma unroll
        for (int off = 16; off > 0; off >>= 1) {
            ws += __shfl_down_sync(FULL, ws, off);
            wq += __shfl_down_sync(FULL, wq, off);
            wc += __shfl_down_sync(FULL, wc, off);
        }
        if (l == 0) {
            const double n    = (double)(bc - wc);
            const double sum  = bs - ws;
            const double sqs  = bq - wq;
            const double mean = sum / n;
            const double var  = (sqs - n * mean * mean) / (n - 1.0);
            const float  stdv = (float)sqrt(var);
            spsr[w] = (float)(((double)bmx - mean)) / (stdv + 1e-5f);
        }
    }
    __syncthreads();
    if (threadIdx.x == 0) {
        float acc = 0.f;
        #pragma unroll
        for (int i = 0; i < BATCH; i++) acc += spsr[i];
        out[0] = acc / (float)BATCH;
        g_counter = 0;   // only block left; safe reset for next graph replay
    }
}

extern "C" void kernel_launch(void* const* d_in, const int* in_sizes, int n_in,
                              void* d_out, int out_size) {
    const float* resp = (const float*)d_in[0];
    float* out = (float*)d_out;
    dim3 grid(BPB, BATCH);
    psr_fused<<<grid, T1>>>(resp, out);
}

// round 7
// speedup vs baseline: 1.1757x; 1.0315x over previous
#include <cuda_runtime.h>
#include <math.h>

#define HH 2048
#define WW 2048
#define NPB (HH*WW)            // 4,194,304 elems per batch
#define BATCH 8
#define BPB 128                // blocks per batch
#define T1 256                 // threads per block
#define NBLK (BPB*BATCH)       // 1024 total blocks
#define STRIDE (BPB*T1)        // 32768 threads per batch (float4 units)
#define ITERS (NPB/4/STRIDE)   // 32 float4 loads per thread, exact
#define WIN 5

// Scratch (device globals — no allocation in kernel_launch)
__device__ float g_pmax[NBLK];
__device__ int   g_pidx[NBLK];
__device__ float g_psum[NBLK];
__device__ float g_psq [NBLK];
__device__ int   g_pcnt[NBLK];
__device__ int   g_counter;      // zero-init; reset by the last block each run

__global__ void __launch_bounds__(T1, 8) psr_fused(const float* __restrict__ resp,
                                                   float* __restrict__ out) {
    const int b   = blockIdx.y;
    const int tid = blockIdx.x * T1 + threadIdx.x;       // 0..STRIDE-1 within batch
    const float4* __restrict__ p = (const float4*)(resp + (size_t)b * NPB);

    float mx = -INFINITY;
    int   midx = 0;
    float s = 0.f, sq = 0.f; int c = 0;

    // R4 stream loop (matches R1 bandwidth): plain grid-walk, rare-branch argmax.
    #pragma unroll 4
    for (int k = 0; k < ITERS; k++) {
        const int i = tid + k * STRIDE;
        const float4 v = p[(size_t)i];
        float m;
        m = fmaxf(v.x, 0.f); s += m; sq = fmaf(m, m, sq); c += (v.x > 0.f);
        m = fmaxf(v.y, 0.f); s += m; sq = fmaf(m, m, sq); c += (v.y > 0.f);
        m = fmaxf(v.z, 0.f); s += m; sq = fmaf(m, m, sq); c += (v.z > 0.f);
        m = fmaxf(v.w, 0.f); s += m; sq = fmaf(m, m, sq); c += (v.w > 0.f);
        const float vm = fmaxf(fmaxf(v.x, v.y), fmaxf(v.z, v.w));
        if (vm > mx) {                                   // rare (~log ITERS times)
            mx = vm;
            int comp = 3;
            if (v.z == vm) comp = 2;
            if (v.y == vm) comp = 1;
            if (v.x == vm) comp = 0;
            midx = i * 4 + comp;
        }
    }

    // ---- intra-warp reduce ----
    const unsigned FULL = 0xFFFFFFFFu;
    #pragma unroll
    for (int off = 16; off > 0; off >>= 1) {
        float om = __shfl_down_sync(FULL, mx, off);
        int   oi = __shfl_down_sync(FULL, midx, off);
        if (om > mx || (om == mx && oi < midx)) { mx = om; midx = oi; }
        s  += __shfl_down_sync(FULL, s,  off);
        sq += __shfl_down_sync(FULL, sq, off);
        c  += __shfl_down_sync(FULL, c,  off);
    }

    // ---- cross-warp reduce via smem (8 warps) ----
    __shared__ float wmax[8]; __shared__ int widx[8];
    __shared__ float wsum[8]; __shared__ float wsq[8]; __shared__ int wcnt[8];
    const int lane = threadIdx.x & 31;
    const int wid  = threadIdx.x >> 5;
    if (lane == 0) { wmax[wid] = mx; widx[wid] = midx; wsum[wid] = s; wsq[wid] = sq; wcnt[wid] = c; }
    __syncthreads();

    if (wid == 0) {
        mx   = (lane < 8) ? wmax[lane] : -INFINITY;
        midx = (lane < 8) ? widx[lane] : 0x7FFFFFFF;
        s    = (lane < 8) ? wsum[lane] : 0.f;
        sq   = (lane < 8) ? wsq[lane]  : 0.f;
        c    = (lane < 8) ? wcnt[lane] : 0;
        #pragma unroll
        for (int off = 4; off > 0; off >>= 1) {
            float om = __shfl_down_sync(FULL, mx, off);
            int   oi = __shfl_down_sync(FULL, midx, off);
            if (om > mx || (om == mx && oi < midx)) { mx = om; midx = oi; }
            s  += __shfl_down_sync(FULL, s,  off);
            sq += __shfl_down_sync(FULL, sq, off);
            c  += __shfl_down_sync(FULL, c,  off);
        }
        if (lane == 0) {
            const int o = b * BPB + blockIdx.x;
            g_pmax[o] = mx; g_pidx[o] = midx; g_psum[o] = s; g_psq[o] = sq; g_pcnt[o] = c;
        }
    }

    // ---- last-block-done ----
    __shared__ int is_last;
    __threadfence();
    __syncthreads();
    if (threadIdx.x == 0) {
        int prev = atomicAdd(&g_counter, 1);
        is_last = (prev == NBLK - 1);
    }
    __syncthreads();
    if (!is_last) return;

    // ================= finalize (parallel, float tree reductions) =============
    __shared__ float fmx [NBLK];
    __shared__ int   fidx[NBLK];
    __shared__ float fsum[NBLK];
    __shared__ float fsq [NBLK];
    __shared__ int   fcnt[NBLK];
    __shared__ float spsr[8];

    // Stage all partials into smem in one parallel burst (20 indep loads/thread).
    #pragma unroll
    for (int j = threadIdx.x; j < NBLK; j += T1) {
        fmx [j] = g_pmax[j];
        fidx[j] = g_pidx[j];
        fsum[j] = g_psum[j];
        fsq [j] = g_psq[j];
        fcnt[j] = g_pcnt[j];
    }
    __syncthreads();

    {
        const int w = threadIdx.x >> 5;     // batch
        const int l = threadIdx.x & 31;

        float bmx = -INFINITY; int bmi = 0x7FFFFFFF;
        float bs = 0.f, bq = 0.f; int bc = 0;
        #pragma unroll
        for (int t = 0; t < 4; t++) {
            const int o = w * BPB + l + t * 32;
            const float pm = fmx[o]; const int pi = fidx[o];
            if (pm > bmx || (pm == bmx && pi < bmi)) { bmx = pm; bmi = pi; }
            bs += fsum[o]; bq += fsq[o]; bc += fcnt[o];
        }
        #pragma unroll
        for (int off = 16; off > 0; off >>= 1) {
            float om = __shfl_down_sync(FULL, bmx, off);
            int   oi = __shfl_down_sync(FULL, bmi, off);
            if (om > bmx || (om == bmx && oi < bmi)) { bmx = om; bmi = oi; }
            bs += __shfl_down_sync(FULL, bs, off);
            bq += __shfl_down_sync(FULL, bq, off);
            bc += __shfl_down_sync(FULL, bc, off);
        }
        bmi = __shfl_sync(FULL, bmi, 0);
        const int cy = bmi / WW, cx = bmi % WW;

        // 11x11 window correction: 121 elems over 32 lanes, 4 indep loads/lane.
        float ws = 0.f, wq = 0.f; int wc = 0;
        #pragma unroll
        for (int t = 0; t < 4; t++) {
            const int it = l + t * 32;
            if (it < (2*WIN+1)*(2*WIN+1)) {
                const int y = cy + it / (2*WIN+1) - WIN;
                const int x = cx + it % (2*WIN+1) - WIN;
                if (y >= 0 && y < HH && x >= 0 && x < WW) {
                    const float v = resp[(size_t)w * NPB + (size_t)y * WW + x];
                    if (v > 0.f) { ws += v; wq = fmaf(v, v, wq); wc++; }
                }
            }
        }
        #pragma unroll
        for (int off = 16; off > 0; off >>= 1) {
            ws += __shfl_down_sync(FULL, ws, off);
            wq += __shfl_down_sync(FULL, wq, off);
            wc += __shfl_down_sync(FULL, wc, off);
        }
        if (l == 0) {
            const double n    = (double)(bc - wc);
            const double sum  = (double)bs - (double)ws;
            const double sqs  = (double)bq - (double)wq;
            const double mean = sum / n;
            const double var  = (sqs - n * mean * mean) / (n - 1.0);
            const float  stdv = (float)sqrt(var);
            spsr[w] = (float)((double)bmx - mean) / (stdv + 1e-5f);
        }
    }
    __syncthreads();
    if (threadIdx.x == 0) {
        float acc = 0.f;
        #pragma unroll
        for (int i = 0; i < BATCH; i++) acc += spsr[i];
        out[0] = acc / (float)BATCH;
        g_counter = 0;   // only block left; safe reset for next graph replay
    }
}

extern "C" void kernel_launch(void* const* d_in, const int* in_sizes, int n_in,
                              void* d_out, int out_size) {
    const float* resp = (const float*)d_in[0];
    float* out = (float*)d_out;
    dim3 grid(BPB, BATCH);
    psr_fused<<<grid, T1>>>(resp, out);
}

// round 8
// speedup vs baseline: 1.1837x; 1.0067x over previous
#include <cuda_runtime.h>
#include <math.h>
#include <cstdint>

#define HH 2048
#define WW 2048
#define NPB (HH*WW)            // 4,194,304 elems per batch
#define BATCH 8
#define BPB 128                // blocks per batch
#define T1 256                 // threads per block
#define NBLK (BPB*BATCH)       // 1024 total blocks
#define STRIDE (BPB*T1)        // 32768 threads per batch (float4 units)
#define ITERS (NPB/4/STRIDE)   // 32 float4 loads per thread, exact
#define STAGES 6               // cp.async pipeline depth (24 KB smem)
#define WIN 5

// Scratch (device globals — no allocation in kernel_launch)
__device__ float g_pmax[NBLK];
__device__ int   g_pidx[NBLK];
__device__ float g_psum[NBLK];
__device__ float g_psq [NBLK];
__device__ int   g_pcnt[NBLK];
__device__ int   g_counter;      // zero-init; reset by the last block each run

__device__ __forceinline__ void cp16(uint32_t smem_dst, const void* gsrc) {
    asm volatile("cp.async.cg.shared.global [%0], [%1], 16;"
                 :: "r"(smem_dst), "l"(gsrc) : "memory");
}
__device__ __forceinline__ void cp_commit() {
    asm volatile("cp.async.commit_group;" ::: "memory");
}

__global__ void __launch_bounds__(T1, 7) psr_fused(const float* __restrict__ resp,
                                                   float* __restrict__ out) {
    __shared__ float4 pipe[STAGES * T1];                 // 24 KB ring
    const int b   = blockIdx.y;
    const int tid = blockIdx.x * T1 + threadIdx.x;       // 0..STRIDE-1 within batch
    const float4* __restrict__ p = (const float4*)(resp + (size_t)b * NPB) + tid;

    const uint32_t sbase =
        (uint32_t)__cvta_generic_to_shared(&pipe[threadIdx.x]);

    // ---- prologue: fill STAGES-1 stages ----
    #pragma unroll
    for (int k = 0; k < STAGES - 1; k++) {
        cp16(sbase + k * (T1 * 16), p + (size_t)k * STRIDE);
        cp_commit();
    }

    float mx = -INFINITY;
    int   midx = 0;
    float s = 0.f, sq = 0.f; int c = 0;
    int rd = 0, wr = STAGES - 1;

    #pragma unroll 1
    for (int k = 0; k < ITERS - (STAGES - 1); k++) {
        // issue stage k+STAGES-1
        cp16(sbase + wr * (T1 * 16), p + (size_t)(k + STAGES - 1) * STRIDE);
        cp_commit();
        if (++wr == STAGES) wr = 0;
        // wait until group k complete (groups retire in order; <=STAGES-1 pending)
        asm volatile("cp.async.wait_group 5;" ::: "memory");

        const float4 v = pipe[rd * T1 + threadIdx.x];
        if (++rd == STAGES) rd = 0;

        const int i = tid + k * STRIDE;
        float m;
        m = fmaxf(v.x, 0.f); s += m; sq = fmaf(m, m, sq); c += (v.x > 0.f);
        m = fmaxf(v.y, 0.f); s += m; sq = fmaf(m, m, sq); c += (v.y > 0.f);
        m = fmaxf(v.z, 0.f); s += m; sq = fmaf(m, m, sq); c += (v.z > 0.f);
        m = fmaxf(v.w, 0.f); s += m; sq = fmaf(m, m, sq); c += (v.w > 0.f);
        const float vm = fmaxf(fmaxf(v.x, v.y), fmaxf(v.z, v.w));
        if (vm > mx) {                                   // rare
            mx = vm;
            int comp = 3;
            if (v.z == vm) comp = 2;
            if (v.y == vm) comp = 1;
            if (v.x == vm) comp = 0;
            midx = i * 4 + comp;
        }
    }

    // ---- drain tail stages ----
    asm volatile("cp.async.wait_group 0;" ::: "memory");
    #pragma unroll
    for (int k = ITERS - (STAGES - 1); k < ITERS; k++) {
        const float4 v = pipe[rd * T1 + threadIdx.x];
        if (++rd == STAGES) rd = 0;
        const int i = tid + k * STRIDE;
        float m;
        m = fmaxf(v.x, 0.f); s += m; sq = fmaf(m, m, sq); c += (v.x > 0.f);
        m = fmaxf(v.y, 0.f); s += m; sq = fmaf(m, m, sq); c += (v.y > 0.f);
        m = fmaxf(v.z, 0.f); s += m; sq = fmaf(m, m, sq); c += (v.z > 0.f);
        m = fmaxf(v.w, 0.f); s += m; sq = fmaf(m, m, sq); c += (v.w > 0.f);
        const float vm = fmaxf(fmaxf(v.x, v.y), fmaxf(v.z, v.w));
        if (vm > mx) {
            mx = vm;
            int comp = 3;
            if (v.z == vm) comp = 2;
            if (v.y == vm) comp = 1;
            if (v.x == vm) comp = 0;
            midx = i * 4 + comp;
        }
    }

    // ---- intra-warp reduce ----
    const unsigned FULL = 0xFFFFFFFFu;
    #pragma unroll
    for (int off = 16; off > 0; off >>= 1) {
        float om = __shfl_down_sync(FULL, mx, off);
        int   oi = __shfl_down_sync(FULL, midx, off);
        if (om > mx || (om == mx && oi < midx)) { mx = om; midx = oi; }
        s  += __shfl_down_sync(FULL, s,  off);
        sq += __shfl_down_sync(FULL, sq, off);
        c  += __shfl_down_sync(FULL, c,  off);
    }

    // ---- cross-warp reduce via smem (8 warps) ----
    __shared__ float wmax[8]; __shared__ int widx[8];
    __shared__ float wsum[8]; __shared__ float wsq[8]; __shared__ int wcnt[8];
    const int lane = threadIdx.x & 31;
    const int wid  = threadIdx.x >> 5;
    if (lane == 0) { wmax[wid] = mx; widx[wid] = midx; wsum[wid] = s; wsq[wid] = sq; wcnt[wid] = c; }
    __syncthreads();

    if (wid == 0) {
        mx   = (lane < 8) ? wmax[lane] : -INFINITY;
        midx = (lane < 8) ? widx[lane] : 0x7FFFFFFF;
        s    = (lane < 8) ? wsum[lane] : 0.f;
        sq   = (lane < 8) ? wsq[lane]  : 0.f;
        c    = (lane < 8) ? wcnt[lane] : 0;
        #pragma unroll
        for (int off = 4; off > 0; off >>= 1) {
            float om = __shfl_down_sync(FULL, mx, off);
            int   oi = __shfl_down_sync(FULL, midx, off);
            if (om > mx || (om == mx && oi < midx)) { mx = om; midx = oi; }
            s  += __shfl_down_sync(FULL, s,  off);
            sq += __shfl_down_sync(FULL, sq, off);
            c  += __shfl_down_sync(FULL, c,  off);
        }
        if (lane == 0) {
            const int o = b * BPB + blockIdx.x;
            g_pmax[o] = mx; g_pidx[o] = midx; g_psum[o] = s; g_psq[o] = sq; g_pcnt[o] = c;
        }
    }

    // ---- last-block-done ----
    __shared__ int is_last;
    __threadfence();
    __syncthreads();
    if (threadIdx.x == 0) {
        int prev = atomicAdd(&g_counter, 1);
        is_last = (prev == NBLK - 1);
    }
    __syncthreads();
    if (!is_last) return;

    // ================= finalize (aliases the pipeline smem) ===================
    float* fmx  = (float*)pipe;                // [0,1024)
    int*   fidx = (int*)pipe + 1024;           // [1024,2048)
    float* fsum = (float*)pipe + 2048;         // [2048,3072)
    float* fsq  = (float*)pipe + 3072;         // [3072,4096)
    int*   fcnt = (int*)pipe + 4096;           // [4096,5120)  (20 KB <= 24 KB)
    __shared__ float spsr[8];

    #pragma unroll
    for (int j = threadIdx.x; j < NBLK; j += T1) {
        fmx [j] = g_pmax[j];
        fidx[j] = g_pidx[j];
        fsum[j] = g_psum[j];
        fsq [j] = g_psq[j];
        fcnt[j] = g_pcnt[j];
    }
    __syncthreads();

    {
        const int w = threadIdx.x >> 5;     // batch
        const int l = threadIdx.x & 31;

        float bmx = -INFINITY; int bmi = 0x7FFFFFFF;
        float bs = 0.f, bq = 0.f; int bc = 0;
        #pragma unroll
        for (int t = 0; t < 4; t++) {
            const int o = w * BPB + l + t * 32;
            const float pm = fmx[o]; const int pi = fidx[o];
            if (pm > bmx || (pm == bmx && pi < bmi)) { bmx = pm; bmi = pi; }
            bs += fsum[o]; bq += fsq[o]; bc += fcnt[o];
        }
        #pragma unroll
        for (int off = 16; off > 0; off >>= 1) {
            float om = __shfl_down_sync(FULL, bmx, off);
            int   oi = __shfl_down_sync(FULL, bmi, off);
            if (om > bmx || (om == bmx && oi < bmi)) { bmx = om; bmi = oi; }
            bs += __shfl_down_sync(FULL, bs, off);
            bq += __shfl_down_sync(FULL, bq, off);
            bc += __shfl_down_sync(FULL, bc, off);
        }
        bmi = __shfl_sync(FULL, bmi, 0);
        const int cy = bmi / WW, cx = bmi % WW;

        float ws = 0.f, wq = 0.f; int wc = 0;
        #pragma unroll
        for (int t = 0; t < 4; t++) {
            const int it = l + t * 32;
            if (it < (2*WIN+1)*(2*WIN+1)) {
                const int y = cy + it / (2*WIN+1) - WIN;
                const int x = cx + it % (2*WIN+1) - WIN;
                if (y >= 0 && y < HH && x >= 0 && x < WW) {
                    const float v = resp[(size_t)w * NPB + (size_t)y * WW + x];
                    if (v > 0.f) { ws += v; wq = fmaf(v, v, wq); wc++; }
                }
            }
        }
        #pragma unroll
        for (int off = 16; off > 0; off >>= 1) {
            ws += __shfl_down_sync(FULL, ws, off);
            wq += __shfl_down_sync(FULL, wq, off);
            wc += __shfl_down_sync(FULL, wc, off);
        }
        if (l == 0) {
            const double n    = (double)(bc - wc);
            const double sum  = (double)bs - (double)ws;
            const double sqs  = (double)bq - (double)wq;
            const double mean = sum / n;
            const double var  = (sqs - n * mean * mean) / (n - 1.0);
            const float  stdv = (float)sqrt(var);
            spsr[w] = (float)((double)bmx - mean) / (stdv + 1e-5f);
        }
    }
    __syncthreads();
    if (threadIdx.x == 0) {
        float acc = 0.f;
        #pragma unroll
        for (int i = 0; i < BATCH; i++) acc += spsr[i];
        out[0] = acc / (float)BATCH;
        g_counter = 0;   // only block left; safe reset for next graph replay
    }
}

extern "C" void kernel_launch(void* const* d_in, const int* in_sizes, int n_in,
                              void* d_out, int out_size) {
    const float* resp = (const float*)d_in[0];
    float* out = (float*)d_out;
    dim3 grid(BPB, BATCH);
    psr_fused<<<grid, T1>>>(resp, out);
}